// round 2
// baseline (speedup 1.0000x reference)
#include <cuda_runtime.h>
#include <math.h>

#define ENC_LEVELS 80
#define N_LEVELS2 (ENC_LEVELS / 2)

// Scale table: s[i] = fl32( fl32(1.25^i) * fl32(pi) ).
// 1.25^i computed in double by repeated multiply: rel err <= 79*2^-53 ~ 9e-15,
// far below half a float ulp (3e-8), so the float cast is the correctly
// rounded fp32 of 1.25^i — matching a correctly-rounded reference powf.
__device__ float g_scales[ENC_LEVELS];

__global__ void pe_init_scales_kernel() {
    int i = threadIdx.x;
    if (i < ENC_LEVELS) {
        double s = 1.0;
        for (int k = 0; k < i; k++) s *= 1.25;   // exact-ish double product
        float sf = (float)s;                      // correctly rounded 1.25^i (f32)
        g_scales[i] = sf * (float)M_PI;           // f32 multiply by 0x40490FDB
    }
}

// One thread computes 2 adjacent (p, i) pairs -> one float4 {sin,cos,sin,cos}.
// idx = t*2 is even, and ENC_LEVELS is even, so both pairs share the same p.
__global__ void __launch_bounds__(256) pe_main_kernel(float4* __restrict__ out,
                                                      int n_quads) {
    int t = blockIdx.x * blockDim.x + threadIdx.x;
    if (t >= n_quads) return;

    int idx = t * 2;                 // linear (p, level) index, level even
    int p   = idx / ENC_LEVELS;
    int i   = idx - p * ENC_LEVELS;

    float pf = (float)p;
    float s0 = __ldg(&g_scales[i]);
    float s1 = __ldg(&g_scales[i + 1]);

    float v0 = pf * s0;              // single f32 multiply, as in reference
    float v1 = pf * s1;

    float sn, cs;
    float4 r;
    sincosf(v0, &sn, &cs);           // libdevice: exact Payne-Hanek reduction
    r.x = sn; r.y = cs;
    sincosf(v1, &sn, &cs);
    r.z = sn; r.w = cs;

    out[t] = r;
}

extern "C" void kernel_launch(void* const* d_in, const int* in_sizes, int n_in,
                              void* d_out, int out_size) {
    (void)d_in; (void)n_in;           // reference ignores pos values
    int n = in_sizes[0];              // number of positions

    pe_init_scales_kernel<<<1, ENC_LEVELS>>>();

    int n_quads = n * N_LEVELS2;      // total float4 outputs: n * 80 / 2
    int threads = 256;
    int blocks  = (n_quads + threads - 1) / threads;
    pe_main_kernel<<<blocks, threads>>>((float4*)d_out, n_quads);
}

// round 3
// speedup vs baseline: 5.2395x; 5.2395x over previous
#include <cuda_runtime.h>
#include <math.h>

#define ENC_LEVELS 80
#define NPAIRS     (ENC_LEVELS / 2)   // 40 float4 per position

// Per-level tables, filled by init kernel (graph-capturable, no allocs).
__device__ float        g_scales[ENC_LEVELS];             // fl32(fl32(1.25^i)*pi_f)
__device__ unsigned int g_Flo[ENC_LEVELS], g_Fhi[ENC_LEVELS]; // frac(scale/2pi) in 2^-64 fixed pt
__device__ float        g_inv[2];                          // 1/(2pi) as float-float (hi, lo)

__global__ void pe_init_kernel() {
    int i = threadIdx.x;
    if (i == 0) {
        const double inv2pi_d = 0.15915494309189533576888376337251;
        float ih = (float)inv2pi_d;
        float il = (float)(inv2pi_d - (double)ih);
        g_inv[0] = ih; g_inv[1] = il;
    }
    if (i >= ENC_LEVELS) return;

    // 1.25^i by binary powering in double: <= 13 roundings, rel err ~1.5e-15,
    // so the float cast is the correctly rounded fp32 of 1.25^i.
    double b = 1.25, s = 1.0;
    int ii = i;
    while (ii) { if (ii & 1) s *= b; b *= b; ii >>= 1; }
    float sf    = (float)s;
    float scale = sf * (float)M_PI;        // f32 multiply by 0x40490FDB
    g_scales[i] = scale;

    // frac(scale / 2pi) to ~1e-16 via double-double 2pi reduction.
    const double th = 6.283185307179586476925286766559;   // 2pi hi (double)
    const double tl = 2.4492935982947063545e-16;          // 2pi lo
    double S  = (double)scale;                            // exact
    double k  = floor(S / th);
    double r;
    for (;;) {
        double p1 = k * th;
        double p2 = fma(k, th, -p1);       // twoProd: p1+p2 == k*th exactly
        r = ((S - p1) - p2) - k * tl;      // S - k*(2pi), |err| ~ few e-15
        if (r < 0.0)  { k -= 1.0; continue; }
        if (r >= th)  { k += 1.0; continue; }
        break;
    }
    double f = r / th;                     // frac(S/2pi), in [0,1)
    double x = f * 18446744073709551616.0; // f * 2^64
    unsigned long long F;
    if (x >= 18446744073709551616.0) F = 0xFFFFFFFFFFFFFFFFull;
    else                             F = (unsigned long long)x;
    g_Flo[i] = (unsigned int)F;
    g_Fhi[i] = (unsigned int)(F >> 32);
}

// Magic constant for fp32 round-to-nearest-integer via add/sub (RN mode).
#define MAGIC_F  12582912.0f   /* 1.5 * 2^23 */
#define TWO_PI_F 6.28318530717958647692f

// Compute (sin, cos) of fl32(pf * s) without Payne-Hanek:
//   phase_turns = frac(p * frac(s/2pi))  -  (e/2pi mod 1),   e = p*s - fl(p*s) (exact)
__device__ __forceinline__ float2 pe_pair(float pf, unsigned int pu,
                                          float s, unsigned int Flo, unsigned int Fhi,
                                          float ih, float il) {
    // exact fp32 product split
    float v = __fmul_rn(pf, s);
    float e = __fmaf_rn(pf, s, -v);               // exact rounding error of v

    // frac(p * f) via 64-bit fixed point: high word of (p*F mod 2^64)
    unsigned int h = __umulhi(pu, Flo) + pu * Fhi; // natural mod 2^32
    float uf = __uint_as_float(0x3F800000u | (h >> 9)); // 1 + frac (23 bits), exact

    // e/(2pi) mod 1 in float-float
    float yh = __fmul_rn(e, ih);
    float yl = __fmaf_rn(e, ih, -yh);              // twoProd tail (exact)
    float t2 = __fmaf_rn(e, il, yl);
    float m  = __fadd_rn(yh, MAGIC_F);
    float rn = __fadd_rn(m, -MAGIC_F);             // nearest integer to yh
    float fr = __fadd_rn(yh, -rn);                 // exact (Sterbenz)
    float fe = __fadd_rn(fr, t2);                  // e/2pi mod 1, in ~[-0.5, 0.5]

    // combine, wrap to [-0.5, 0.5] turns, convert to radians
    float phi = __fadd_rn(__fadd_rn(uf, -1.0f), -fe);
    float m2  = __fadd_rn(phi, MAGIC_F);
    float r2  = __fadd_rn(m2, -MAGIC_F);
    float pw  = __fadd_rn(phi, -r2);
    float theta = pw * TWO_PI_F;                   // in [-pi, pi]

    float2 sc;
    sc.x = __sinf(theta);                          // MUFU.SIN
    sc.y = __cosf(theta);                          // MUFU.COS
    return sc;
}

// blockDim = (40, 8): lane x owns level pair (2x, 2x+1) -> one float4 per p.
// Grid-stride over positions; tables live in registers across the loop.
__global__ void __launch_bounds__(320) pe_main_kernel(float4* __restrict__ out, int n) {
    int x  = threadIdx.x;                       // 0..39
    int p  = blockIdx.x * 8 + threadIdx.y;
    int ps = gridDim.x * 8;

    float        s0  = __ldg(&g_scales[2 * x]);
    float        s1  = __ldg(&g_scales[2 * x + 1]);
    unsigned int lo0 = __ldg(&g_Flo[2 * x]),     hi0 = __ldg(&g_Fhi[2 * x]);
    unsigned int lo1 = __ldg(&g_Flo[2 * x + 1]), hi1 = __ldg(&g_Fhi[2 * x + 1]);
    float        ih  = __ldg(&g_inv[0]),         il  = __ldg(&g_inv[1]);

    float pf  = (float)p;       // exact: p < 2^24
    float pfs = (float)ps;
    float4* op = out + (size_t)p * NPAIRS + x;
    size_t  os = (size_t)ps * NPAIRS;

    for (; p < n; p += ps, pf += pfs, op += os) {
        unsigned int pu = (unsigned int)p;
        float2 a = pe_pair(pf, pu, s0, lo0, hi0, ih, il);
        float2 b = pe_pair(pf, pu, s1, lo1, hi1, ih, il);
        float4 r; r.x = a.x; r.y = a.y; r.z = b.x; r.w = b.y;
        *op = r;
    }
}

extern "C" void kernel_launch(void* const* d_in, const int* in_sizes, int n_in,
                              void* d_out, int out_size) {
    (void)d_in; (void)n_in; (void)out_size;   // reference ignores pos values
    int n = in_sizes[0];

    pe_init_kernel<<<1, 128>>>();

    const int PY = 8, LOOP = 64;
    int blocks = (n + PY * LOOP - 1) / (PY * LOOP);   // ~977 for n=500000
    if (blocks < 1) blocks = 1;
    dim3 bd(NPAIRS, PY);
    pe_main_kernel<<<blocks, bd>>>((float4*)d_out, n);
}